// round 16
// baseline (speedup 1.0000x reference)
#include <cuda_runtime.h>
#include <cuda_fp16.h>
#include <cstdint>

// Problem constants
#define BATCH 8
#define CDIM 256
#define HH 56
#define WW 56
#define HWPIX (HH * WW)          // 3136
#define NHEADS 8
#define HDIM 32
#define SWID 7
#define NSTRIPE (HH / SWID)      // 8
#define NTOK (SWID * WW)         // 392
// ATTSCALE * log2(e): softmax exp computed as ex2(logit * QSCALE)
#define QSCALE 0.25504079827f
#define HCLAMP14 0x4B004B00u     // half2(14.0, 14.0)

// Scratch (device globals; no allocations allowed). All intermediates f16.
__device__ __half g_xh[BATCH * CDIM * HWPIX];
__device__ __half g_wqh[3 * CDIM * CDIM];
__device__ __half g_wph[CDIM * CDIM];
__device__ __half g_qkvh[BATCH * 3 * CDIM * HWPIX];
__device__ __half g_v2h[BATCH * CDIM * HWPIX];
__device__ __half g_atth[BATCH * CDIM * HWPIX];

__device__ __forceinline__ uint32_t smem_u32(const void* p) {
    return (uint32_t)__cvta_generic_to_shared(p);
}

__device__ __forceinline__ void mma_f16(float c[4], const uint32_t a[4],
                                        const uint32_t b[2]) {
    asm volatile(
        "mma.sync.aligned.m16n8k16.row.col.f32.f16.f16.f32 "
        "{%0,%1,%2,%3}, {%4,%5,%6,%7}, {%8,%9}, {%0,%1,%2,%3};"
        : "+f"(c[0]), "+f"(c[1]), "+f"(c[2]), "+f"(c[3])
        : "r"(a[0]), "r"(a[1]), "r"(a[2]), "r"(a[3]), "r"(b[0]), "r"(b[1]));
}

__device__ __forceinline__ void mma_f16_k8(float c[4], const uint32_t a[2],
                                           uint32_t b) {
    asm volatile(
        "mma.sync.aligned.m16n8k8.row.col.f32.f16.f16.f32 "
        "{%0,%1,%2,%3}, {%4,%5}, {%6}, {%0,%1,%2,%3};"
        : "+f"(c[0]), "+f"(c[1]), "+f"(c[2]), "+f"(c[3])
        : "r"(a[0]), "r"(a[1]), "r"(b));
}

__device__ __forceinline__ void ldsm_x4(uint32_t r[4], uint32_t addr) {
    asm volatile("ldmatrix.sync.aligned.m8n8.x4.shared.b16 {%0,%1,%2,%3}, [%4];"
                 : "=r"(r[0]), "=r"(r[1]), "=r"(r[2]), "=r"(r[3]) : "r"(addr));
}

__device__ __forceinline__ void ldsm_x2(uint32_t r[2], uint32_t addr) {
    asm volatile("ldmatrix.sync.aligned.m8n8.x2.shared.b16 {%0,%1}, [%2];"
                 : "=r"(r[0]), "=r"(r[1]) : "r"(addr));
}

__device__ __forceinline__ void ldsm_x1(uint32_t& r, uint32_t addr) {
    asm volatile("ldmatrix.sync.aligned.m8n8.x1.shared.b16 {%0}, [%1];"
                 : "=r"(r) : "r"(addr));
}

__device__ __forceinline__ void ldsm_x4_t(uint32_t r[4], uint32_t addr) {
    asm volatile("ldmatrix.sync.aligned.m8n8.x4.trans.shared.b16 {%0,%1,%2,%3}, [%4];"
                 : "=r"(r[0]), "=r"(r[1]), "=r"(r[2]), "=r"(r[3]) : "r"(addr));
}

__device__ __forceinline__ void cp16_ca(void* dst, const void* src, bool pred) {
    int sz = pred ? 16 : 0;
    asm volatile("cp.async.ca.shared.global [%0], [%1], 16, %2;"
                 :: "r"(smem_u32(dst)), "l"(src), "r"(sz));
}
__device__ __forceinline__ void cp16_cg(void* dst, const void* src, bool pred) {
    int sz = pred ? 16 : 0;
    asm volatile("cp.async.cg.shared.global [%0], [%1], 16, %2;"
                 :: "r"(smem_u32(dst)), "l"(src), "r"(sz));
}
#define CP_COMMIT() asm volatile("cp.async.commit_group;")

// ---------------------------------------------------------------------------
// fp32 -> fp16 conversion (4 elems/thread)
// ---------------------------------------------------------------------------
__global__ __launch_bounds__(256) void f2h_kernel(const float* __restrict__ in,
                                                  __half* __restrict__ out, int n)
{
    int id = (blockIdx.x * 256 + threadIdx.x) * 4;
    if (id + 3 < n) {
        float4 v = *(const float4*)&in[id];
        __half2 h0 = __floats2half2_rn(v.x, v.y);
        __half2 h1 = __floats2half2_rn(v.z, v.w);
        uint2 u = {*(uint32_t*)&h0, *(uint32_t*)&h1};
        *(uint2*)&out[id] = u;
    } else {
        for (int i = id; i < n; i++) out[i] = __float2half(in[i]);
    }
}

// ---------------------------------------------------------------------------
// FP16 GEMM: block 128(o) x 256(p) x 32(k), 8 warps 2(m)x4(n), warp tile
// 64x64 -> MMA:ldmatrix ratio 1.0 (was 1.5). 3-stage cp.async pipeline,
// dynamic smem (79.5 KB, 1 CTA/SM).
// ---------------------------------------------------------------------------
#define ASTR 40
#define BSTR 264
#define GEMM_A_ELEMS (128 * ASTR)          // 5120 halfs / stage
#define GEMM_B_ELEMS (32 * BSTR)           // 8448 halfs / stage
#define GEMM_SMEM ((3 * (GEMM_A_ELEMS + GEMM_B_ELEMS)) * 2)  // 81408 bytes

template<bool HALF_OUT>
__global__ __launch_bounds__(256, 1) void gemm_f16_kernel(
    const __half* __restrict__ X, const __half* __restrict__ W,
    const float* __restrict__ bias, void* __restrict__ OutV,
    int Kdim, int Odim)
{
    const int p0 = blockIdx.x * 256;
    const int o0 = blockIdx.y * 128;
    const int b  = blockIdx.z;

    const __half* Xb = X + (size_t)b * Kdim * HWPIX;

    extern __shared__ __half gsh[];
    __half* Asb = gsh;
    __half* Bsb = gsh + 3 * GEMM_A_ELEMS;

    const int tid = threadIdx.x;
    const int wid = tid >> 5;
    const int lane = tid & 31;
    const int wm = wid & 1;          // 2 m-warps (64 rows each)
    const int wn = wid >> 1;         // 4 n-warps (64 cols each)
    const int lr = lane >> 2;
    const int lc = lane & 3;

    float acc[4][8][4];
    #pragma unroll
    for (int i = 0; i < 4; i++)
        #pragma unroll
        for (int j = 0; j < 8; j++)
            #pragma unroll
            for (int r = 0; r < 4; r++) acc[i][j][r] = 0.f;

    const int nkt = Kdim / 32;

    auto stage = [&](int kt, int buf) {
        const int k0 = kt * 32;
        __half* As = Asb + buf * GEMM_A_ELEMS;
        __half* Bs = Bsb + buf * GEMM_B_ELEMS;
        // A: 128 rows x 32 k = 512 x 16B
        #pragma unroll
        for (int i = 0; i < 2; i++) {
            int id = tid + i * 256;
            int o = id >> 2;
            int c8 = (id & 3) * 8;
            cp16_ca(&As[o * ASTR + c8],
                    &W[(size_t)(o0 + o) * Kdim + k0 + c8], true);
        }
        // B: 32 rows x 256 p = 1024 x 16B
        #pragma unroll
        for (int i = 0; i < 4; i++) {
            int id = tid + i * 256;
            int row = id >> 5;
            int ch = (id & 31) * 8;
            bool ok = (p0 + ch) < HWPIX;
            int col = ok ? (p0 + ch) : (HWPIX - 8);
            cp16_cg(&Bs[row * BSTR + ch],
                    &Xb[(size_t)(k0 + row) * HWPIX + col], ok);
        }
        CP_COMMIT();
    };

    stage(0, 0);
    if (nkt > 1) stage(1, 1);
    for (int kt = 0; kt < nkt; kt++) {
        const int buf = kt % 3;
        if (kt + 2 < nkt) {
            stage(kt + 2, (kt + 2) % 3);
            asm volatile("cp.async.wait_group 2;");
        } else if (kt + 1 < nkt) {
            asm volatile("cp.async.wait_group 1;");
        } else {
            asm volatile("cp.async.wait_group 0;");
        }
        __syncthreads();

        __half* As = Asb + buf * GEMM_A_ELEMS;
        __half* Bs = Bsb + buf * GEMM_B_ELEMS;

        #pragma unroll
        for (int kk = 0; kk < 32; kk += 16) {
            uint32_t af[4][4];
            #pragma unroll
            for (int mf = 0; mf < 4; mf++) {
                int row = wm * 64 + mf * 16 + (lane & 15);
                int kof = kk + (lane >> 4) * 8;
                ldsm_x4(af[mf], smem_u32(&As[row * ASTR + kof]));
            }
            uint32_t bf[4][4];
            #pragma unroll
            for (int g = 0; g < 4; g++) {
                int krow = kk + (lane & 15);
                int ncol = wn * 64 + g * 16 + (lane >> 4) * 8;
                ldsm_x4_t(bf[g], smem_u32(&Bs[krow * BSTR + ncol]));
            }
            #pragma unroll
            for (int mf = 0; mf < 4; mf++)
                #pragma unroll
                for (int nf = 0; nf < 8; nf++) {
                    uint32_t bb[2] = {bf[nf >> 1][(nf & 1) * 2],
                                      bf[nf >> 1][(nf & 1) * 2 + 1]};
                    mma_f16(acc[mf][nf], af[mf], bb);
                }
        }
        __syncthreads();
    }

    #pragma unroll
    for (int mf = 0; mf < 4; mf++) {
        int m = o0 + wm * 64 + mf * 16 + lr;
        float bv0 = bias[m];
        float bv1 = bias[m + 8];
        #pragma unroll
        for (int nf = 0; nf < 8; nf++) {
            int n = p0 + wn * 64 + nf * 8 + 2 * lc;
            if (n < HWPIX) {
                if (HALF_OUT) {
                    __half* Ob = (__half*)OutV + (size_t)b * Odim * HWPIX;
                    __half2 r0 = __floats2half2_rn(acc[mf][nf][0] + bv0,
                                                   acc[mf][nf][1] + bv0);
                    __half2 r1 = __floats2half2_rn(acc[mf][nf][2] + bv1,
                                                   acc[mf][nf][3] + bv1);
                    *(__half2*)&Ob[(size_t)m * HWPIX + n] = r0;
                    *(__half2*)&Ob[(size_t)(m + 8) * HWPIX + n] = r1;
                } else {
                    float* Ob = (float*)OutV + (size_t)b * Odim * HWPIX;
                    float2 r0 = {acc[mf][nf][0] + bv0, acc[mf][nf][1] + bv0};
                    float2 r1 = {acc[mf][nf][2] + bv1, acc[mf][nf][3] + bv1};
                    *(float2*)&Ob[(size_t)m * HWPIX + n] = r0;
                    *(float2*)&Ob[(size_t)(m + 8) * HWPIX + n] = r1;
                }
            }
        }
    }
}

// ---------------------------------------------------------------------------
// Depthwise 3x3 (SAME) on half data, 4 px per thread (unchanged)
// ---------------------------------------------------------------------------
__global__ __launch_bounds__(256) void dwconv_kernel(
    const float* __restrict__ wdw, const float* __restrict__ bdw)
{
    int idx = blockIdx.x * blockDim.x + threadIdx.x;
    if (idx >= BATCH * CDIM * HH * (WW / 4)) return;
    int w0 = (idx % (WW / 4)) * 4;
    int h  = (idx / (WW / 4)) % HH;
    int c  = (idx / (WW / 4 * HH)) % CDIM;
    int b  = idx / (WW / 4 * HH * CDIM);

    const __half* v = g_qkvh + ((size_t)b * 3 * CDIM + 2 * CDIM + c) * HWPIX;

    float r[3][6];
    #pragma unroll
    for (int dy = 0; dy < 3; dy++) {
        int hh = h + dy - 1;
        if (hh >= 0 && hh < HH) {
            const __half* row = v + hh * WW;
            __half2 m0 = *(const __half2*)&row[w0];
            __half2 m1 = *(const __half2*)&row[w0 + 2];
            r[dy][0] = (w0 > 0) ? __half2float(row[w0 - 1]) : 0.f;
            r[dy][1] = __half2float(__low2half(m0));
            r[dy][2] = __half2float(__high2half(m0));
            r[dy][3] = __half2float(__low2half(m1));
            r[dy][4] = __half2float(__high2half(m1));
            r[dy][5] = (w0 + 4 < WW) ? __half2float(row[w0 + 4]) : 0.f;
        } else {
            #pragma unroll
            for (int j = 0; j < 6; j++) r[dy][j] = 0.f;
        }
    }

    float wv[3][3];
    #pragma unroll
    for (int dy = 0; dy < 3; dy++)
        #pragma unroll
        for (int dx = 0; dx < 3; dx++)
            wv[dy][dx] = wdw[c * 9 + dy * 3 + dx];

    float bb = bdw[c];
    float o[4];
    #pragma unroll
    for (int j = 0; j < 4; j++) {
        float s = bb + r[1][j + 1];
        #pragma unroll
        for (int dy = 0; dy < 3; dy++)
            #pragma unroll
            for (int dx = 0; dx < 3; dx++)
                s += wv[dy][dx] * r[dy][j + dx];
        o[j] = s;
    }

    __half* out = g_v2h + ((size_t)b * CDIM + c) * HWPIX + h * WW + w0;
    __half2 o0 = __floats2half2_rn(o[0], o[1]);
    __half2 o1 = __floats2half2_rn(o[2], o[3]);
    *(__half2*)&out[0] = o0;
    *(__half2*)&out[2] = o1;
}

// ---------------------------------------------------------------------------
// FP16 stripe attention (exact R12 best-kernel version): lean mainloop,
// ldmatrix K/V frags, f16x2 softmax, ones-row rowsum via PV MMA.
// 13 warps, 16-row q-tiles (2 rounds).
// ---------------------------------------------------------------------------
#define KHS 40
#define VTS 408
#define VROWS_V 40           // 32 data + ones row + 7 zero rows
#define OTS 400
#define QROWS 400            // 392 + 8 pad rows (zeros)
#define ATT_THREADS 416      // 13 warps
#define ATT_Q_OFF 0
#define ATT_K_OFF (QROWS * KHS)
#define ATT_V_OFF (2 * QROWS * KHS)
#define ATT_O_OFF (2 * QROWS * KHS + VROWS_V * VTS)
#define ATT_SMEM ((2 * QROWS * KHS + VROWS_V * VTS + HDIM * OTS) * 2)

__global__ __launch_bounds__(ATT_THREADS, 1) void attn_mma_kernel()
{
    extern __shared__ __half shh[];
    __half* Qsh  = shh + ATT_Q_OFF;   // [400][40]  (token-major, pre-scaled)
    __half* Ksh  = shh + ATT_K_OFF;   // [400][40]
    __half* Vt   = shh + ATT_V_OFF;   // [40][408]  (channel-major + ones row)
    __half* OshT = shh + ATT_O_OFF;   // [32][400]

    const int s = blockIdx.x;
    const int head = blockIdx.y;
    const int b = blockIdx.z;
    const bool wmode = (head >= NHEADS / 2);

    const int tid = threadIdx.x;
    const int wid = tid >> 5;
    const int lane = tid & 31;
    const int lr = lane >> 2;
    const int lc = lane & 3;

    const __half* qbase = g_qkvh + ((size_t)b * 3 * CDIM + head * HDIM) * HWPIX;
    const __half* kbase = g_qkvh + ((size_t)b * 3 * CDIM + CDIM + head * HDIM) * HWPIX;
    const __half* vbase = g_v2h + ((size_t)b * CDIM + head * HDIM) * HWPIX;

    if (!wmode) {
        const int s392 = s * NTOK;
        for (int idx = tid; idx < HDIM * (NTOK / 8); idx += ATT_THREADS) {
            int c = idx / (NTOK / 8);
            int t0 = (idx - c * (NTOK / 8)) * 8;
            size_t g = (size_t)c * HWPIX + s392 + t0;
            uint4 q8 = *(const uint4*)(qbase + g);
            uint4 k8 = *(const uint4*)(kbase + g);
            uint4 v8 = *(const uint4*)(vbase + g);
            const __half* qh = (const __half*)&q8;
            const __half* kh = (const __half*)&k8;
            #pragma unroll
            for (int j = 0; j < 8; j++) {
                Qsh[(t0 + j) * KHS + c] =
                    __float2half(__half2float(qh[j]) * QSCALE);
                Ksh[(t0 + j) * KHS + c] = kh[j];
            }
            *(uint4*)(Vt + c * VTS + t0) = v8;
        }
    } else {
        for (int idx = tid; idx < NTOK * HDIM; idx += ATT_THREADS) {
            int c = idx / NTOK;
            int r = idx - c * NTOK;
            int rq = r / SWID;
            int pix = rq * WW + s * SWID + (r - rq * SWID);
            size_t g = (size_t)c * HWPIX + pix;
            Qsh[r * KHS + c] = __float2half(__half2float(qbase[g]) * QSCALE);
            Ksh[r * KHS + c] = kbase[g];
            Vt[c * VTS + r] = vbase[g];
        }
    }
    // Zero Q pad rows 392..399
    for (int idx = tid; idx < (QROWS - NTOK) * KHS; idx += ATT_THREADS)
        Qsh[NTOK * KHS + idx] = __half(0.f);
    // V rows 32..39: row 32 = ones (rowsum column), rows 33..39 = zero
    for (int idx = tid; idx < (VROWS_V - HDIM) * VTS; idx += ATT_THREADS) {
        int rr = idx / VTS;
        Vt[(HDIM + rr) * VTS + (idx - rr * VTS)] =
            (rr == 0) ? __half(1.f) : __half(0.f);
    }
    __syncthreads();

    for (int mt = wid; mt < 25; mt += 13) {
        int q0 = mt * 16;

        uint32_t aq[2][4];
        #pragma unroll
        for (int kf = 0; kf < 2; kf++)
            ldsm_x4(aq[kf], smem_u32(&Qsh[(q0 + (lane & 15)) * KHS +
                                          kf * 16 + (lane >> 4) * 8]));

        float oacc[5][4];
        #pragma unroll
        for (int i = 0; i < 5; i++)
            #pragma unroll
            for (int j = 0; j < 4; j++) oacc[i][j] = 0.f;

        const int g2 = lane >> 3;       // 0..3
        const int r8 = lane & 7;        // 0..7
        const int l16 = lane & 15;

        for (int kt = 0; kt < 7; kt++) {
            const int t0 = kt * 56;
            uint32_t pA[3][4];
            uint32_t pA8[2];

            // S = Q @ K^T per 8-token n-tile; f16x2 softmax; pack A-frags
            #pragma unroll
            for (int nf = 0; nf < 7; nf++) {
                float sf4[4] = {0.f, 0.f, 0.f, 0.f};
                uint32_t kb[4];
                ldsm_x4(kb, smem_u32(&Ksh[(t0 + nf * 8 + r8) * KHS + g2 * 8]));
                {
                    uint32_t b0[2] = {kb[0], kb[1]};
                    uint32_t b1[2] = {kb[2], kb[3]};
                    mma_f16(sf4, aq[0], b0);
                    mma_f16(sf4, aq[1], b1);
                }
                uint32_t u01, u23;
                asm("cvt.rn.f16x2.f32 %0, %1, %2;"
                    : "=r"(u01) : "f"(sf4[1]), "f"(sf4[0]));
                asm("cvt.rn.f16x2.f32 %0, %1, %2;"
                    : "=r"(u23) : "f"(sf4[3]), "f"(sf4[2]));
                asm("min.f16x2 %0, %0, %1;" : "+r"(u01) : "r"(HCLAMP14));
                asm("min.f16x2 %0, %0, %1;" : "+r"(u23) : "r"(HCLAMP14));
                asm("ex2.approx.f16x2 %0, %0;" : "+r"(u01));
                asm("ex2.approx.f16x2 %0, %0;" : "+r"(u23));
                if (nf == 6) {
                    pA8[0] = u01; pA8[1] = u23;
                } else if ((nf & 1) == 0) {
                    pA[nf >> 1][0] = u01; pA[nf >> 1][1] = u23;
                } else {
                    pA[nf >> 1][2] = u01; pA[nf >> 1][3] = u23;
                }
            }

            // O += P @ V (V b-frags via ldmatrix; vf=4 = rowsum column)
            #pragma unroll
            for (int ch = 0; ch < 3; ch++) {
                const int colb = t0 + ch * 16;
                uint32_t v0[4], v1[4], v2[2];
                ldsm_x4(v0, smem_u32(&Vt[((g2 >> 1) * 8 + r8) * VTS +
                                         colb + (g2 & 1) * 8]));
                ldsm_x4(v1, smem_u32(&Vt[(16 + (g2 >> 1) * 8 + r8) * VTS +
                                         colb + (g2 & 1) * 8]));
                ldsm_x2(v2, smem_u32(&Vt[(HDIM + (l16 & 7)) * VTS +
                                         colb + (l16 >> 3) * 8]));
                {
                    uint32_t b0[2] = {v0[0], v0[1]};
                    uint32_t b1[2] = {v0[2], v0[3]};
                    uint32_t b2[2] = {v1[0], v1[1]};
                    uint32_t b3[2] = {v1[2], v1[3]};
                    uint32_t b4[2] = {v2[0], v2[1]};
                    mma_f16(oacc[0], pA[ch], b0);
                    mma_f16(oacc[1], pA[ch], b1);
                    mma_f16(oacc[2], pA[ch], b2);
                    mma_f16(oacc[3], pA[ch], b3);
                    mma_f16(oacc[4], pA[ch], b4);
                }
            }
            // k8 tail (tokens t0+48..55)
            {
                uint32_t w4[4], w1;
                ldsm_x4(w4, smem_u32(&Vt[(g2 * 8 + r8) * VTS + t0 + 48]));
                ldsm_x1(w1, smem_u32(&Vt[(HDIM + r8) * VTS + t0 + 48]));
                mma_f16_k8(oacc[0], pA8, w4[0]);
                mma_f16_k8(oacc[1], pA8, w4[1]);
                mma_f16_k8(oacc[2], pA8, w4[2]);
                mma_f16_k8(oacc[3], pA8, w4[3]);
                mma_f16_k8(oacc[4], pA8, w1);
            }
        }

        // l lives in output column 32: lanes with lc==0, reg oacc[4][0]/[2]
        float l0 = __shfl_sync(0xffffffffu, oacc[4][0], lane & 28);
        float l1 = __shfl_sync(0xffffffffu, oacc[4][2], lane & 28);
        float inv0 = 1.f / l0, inv1 = 1.f / l1;

        int r0 = q0 + lr, r1 = q0 + lr + 8;
        #pragma unroll
        for (int nf = 0; nf < 4; nf++) {
            int c = nf * 8 + 2 * lc;
            OshT[c * OTS + r0]       = __float2half(oacc[nf][0] * inv0);
            OshT[(c + 1) * OTS + r0] = __float2half(oacc[nf][1] * inv0);
            OshT[c * OTS + r1]       = __float2half(oacc[nf][2] * inv1);
            OshT[(c + 1) * OTS + r1] = __float2half(oacc[nf][3] * inv1);
        }
    }
    __syncthreads();

    // Writeback
    __half* obase = g_atth + ((size_t)b * CDIM + head * HDIM) * HWPIX;
    if (!wmode) {
        const int s392 = s * NTOK;
        for (int idx = tid; idx < HDIM * (NTOK / 8); idx += ATT_THREADS) {
            int c = idx / (NTOK / 8);
            int t0 = (idx - c * (NTOK / 8)) * 8;
            uint4 o8 = *(const uint4*)(OshT + c * OTS + t0);
            *(uint4*)(obase + (size_t)c * HWPIX + s392 + t0) = o8;
        }
    } else {
        for (int idx = tid; idx < NTOK * HDIM; idx += ATT_THREADS) {
            int c = idx / NTOK;
            int r = idx - c * NTOK;
            int rq = r / SWID;
            int pix = rq * WW + s * SWID + (r - rq * SWID);
            obase[(size_t)c * HWPIX + pix] = OshT[c * OTS + r];
        }
    }
}

// ---------------------------------------------------------------------------
extern "C" void kernel_launch(void* const* d_in, const int* in_sizes, int n_in,
                              void* d_out, int out_size)
{
    const float* x      = (const float*)d_in[0];
    const float* w_qkv  = (const float*)d_in[1];
    const float* b_qkv  = (const float*)d_in[2];
    const float* w_dw   = (const float*)d_in[3];
    const float* b_dw   = (const float*)d_in[4];
    const float* w_proj = (const float*)d_in[5];
    const float* b_proj = (const float*)d_in[6];
    float* out = (float*)d_out;

    __half* xh;   cudaGetSymbolAddress((void**)&xh, g_xh);
    __half* wqh;  cudaGetSymbolAddress((void**)&wqh, g_wqh);
    __half* wph;  cudaGetSymbolAddress((void**)&wph, g_wph);
    __half* qkvh; cudaGetSymbolAddress((void**)&qkvh, g_qkvh);
    __half* atth; cudaGetSymbolAddress((void**)&atth, g_atth);

    cudaFuncSetAttribute(gemm_f16_kernel<true>,
                         cudaFuncAttributeMaxDynamicSharedMemorySize, GEMM_SMEM);
    cudaFuncSetAttribute(gemm_f16_kernel<false>,
                         cudaFuncAttributeMaxDynamicSharedMemorySize, GEMM_SMEM);
    cudaFuncSetAttribute(attn_mma_kernel,
                         cudaFuncAttributeMaxDynamicSharedMemorySize, ATT_SMEM);

    // 0. convert inputs to half
    {
        int n = BATCH * CDIM * HWPIX;
        f2h_kernel<<<(n / 4 + 255) / 256, 256>>>(x, xh, n);
        n = 3 * CDIM * CDIM;
        f2h_kernel<<<(n / 4 + 255) / 256, 256>>>(w_qkv, wqh, n);
        n = CDIM * CDIM;
        f2h_kernel<<<(n / 4 + 255) / 256, 256>>>(w_proj, wph, n);
    }
    // 1. qkv = conv1x1(x) -> half
    {
        dim3 grid((HWPIX + 255) / 256, (3 * CDIM) / 128, BATCH);
        gemm_f16_kernel<true><<<grid, 256, GEMM_SMEM>>>(xh, wqh, b_qkv, qkvh,
                                                        CDIM, 3 * CDIM);
    }
    // 2. v2 = v + dwconv(v)
    {
        int n = BATCH * CDIM * HH * (WW / 4);
        dwconv_kernel<<<(n + 255) / 256, 256>>>(w_dw, b_dw);
    }
    // 3. fp16 stripe attention -> half
    {
        dim3 grid(NSTRIPE, NHEADS, BATCH);
        attn_mma_kernel<<<grid, ATT_THREADS, ATT_SMEM>>>();
    }
    // 4. out = conv1x1(att) -> fp32
    {
        dim3 grid((HWPIX + 255) / 256, CDIM / 128, BATCH);
        gemm_f16_kernel<false><<<grid, 256, GEMM_SMEM>>>(atth, wph, b_proj, out,
                                                         CDIM, CDIM);
    }
}

// round 17
// speedup vs baseline: 1.1279x; 1.1279x over previous
#include <cuda_runtime.h>
#include <cuda_fp16.h>
#include <cstdint>

// Problem constants
#define BATCH 8
#define CDIM 256
#define HH 56
#define WW 56
#define HWPIX (HH * WW)          // 3136
#define NHEADS 8
#define HDIM 32
#define SWID 7
#define NSTRIPE (HH / SWID)      // 8
#define NTOK (SWID * WW)         // 392
// ATTSCALE * log2(e): softmax exp computed as ex2(logit * QSCALE)
#define QSCALE 0.25504079827f
#define HCLAMP14 0x4B004B00u     // half2(14.0, 14.0)

// Scratch (device globals; no allocations allowed). All intermediates f16.
__device__ __half g_xh[BATCH * CDIM * HWPIX];
__device__ __half g_wqh[3 * CDIM * CDIM];
__device__ __half g_wph[CDIM * CDIM];
__device__ __half g_qkvh[BATCH * 3 * CDIM * HWPIX];
__device__ __half g_v2h[BATCH * CDIM * HWPIX];
__device__ __half g_atth[BATCH * CDIM * HWPIX];

__device__ __forceinline__ uint32_t smem_u32(const void* p) {
    return (uint32_t)__cvta_generic_to_shared(p);
}

__device__ __forceinline__ void mma_f16(float c[4], const uint32_t a[4],
                                        const uint32_t b[2]) {
    asm volatile(
        "mma.sync.aligned.m16n8k16.row.col.f32.f16.f16.f32 "
        "{%0,%1,%2,%3}, {%4,%5,%6,%7}, {%8,%9}, {%0,%1,%2,%3};"
        : "+f"(c[0]), "+f"(c[1]), "+f"(c[2]), "+f"(c[3])
        : "r"(a[0]), "r"(a[1]), "r"(a[2]), "r"(a[3]), "r"(b[0]), "r"(b[1]));
}

__device__ __forceinline__ void mma_f16_k8(float c[4], const uint32_t a[2],
                                           uint32_t b) {
    asm volatile(
        "mma.sync.aligned.m16n8k8.row.col.f32.f16.f16.f32 "
        "{%0,%1,%2,%3}, {%4,%5}, {%6}, {%0,%1,%2,%3};"
        : "+f"(c[0]), "+f"(c[1]), "+f"(c[2]), "+f"(c[3])
        : "r"(a[0]), "r"(a[1]), "r"(b));
}

__device__ __forceinline__ void ldsm_x4(uint32_t r[4], uint32_t addr) {
    asm volatile("ldmatrix.sync.aligned.m8n8.x4.shared.b16 {%0,%1,%2,%3}, [%4];"
                 : "=r"(r[0]), "=r"(r[1]), "=r"(r[2]), "=r"(r[3]) : "r"(addr));
}

__device__ __forceinline__ void ldsm_x2(uint32_t r[2], uint32_t addr) {
    asm volatile("ldmatrix.sync.aligned.m8n8.x2.shared.b16 {%0,%1}, [%2];"
                 : "=r"(r[0]), "=r"(r[1]) : "r"(addr));
}

__device__ __forceinline__ void ldsm_x1(uint32_t& r, uint32_t addr) {
    asm volatile("ldmatrix.sync.aligned.m8n8.x1.shared.b16 {%0}, [%1];"
                 : "=r"(r) : "r"(addr));
}

__device__ __forceinline__ void ldsm_x4_t(uint32_t r[4], uint32_t addr) {
    asm volatile("ldmatrix.sync.aligned.m8n8.x4.trans.shared.b16 {%0,%1,%2,%3}, [%4];"
                 : "=r"(r[0]), "=r"(r[1]), "=r"(r[2]), "=r"(r[3]) : "r"(addr));
}

__device__ __forceinline__ void cp16_ca(void* dst, const void* src, bool pred) {
    int sz = pred ? 16 : 0;
    asm volatile("cp.async.ca.shared.global [%0], [%1], 16, %2;"
                 :: "r"(smem_u32(dst)), "l"(src), "r"(sz));
}
__device__ __forceinline__ void cp16_cg(void* dst, const void* src, bool pred) {
    int sz = pred ? 16 : 0;
    asm volatile("cp.async.cg.shared.global [%0], [%1], 16, %2;"
                 :: "r"(smem_u32(dst)), "l"(src), "r"(sz));
}
#define CP_COMMIT() asm volatile("cp.async.commit_group;")

// ---------------------------------------------------------------------------
// fp32 -> fp16 conversion (4 elems/thread)
// ---------------------------------------------------------------------------
__global__ __launch_bounds__(256) void f2h_kernel(const float* __restrict__ in,
                                                  __half* __restrict__ out, int n)
{
    int id = (blockIdx.x * 256 + threadIdx.x) * 4;
    if (id + 3 < n) {
        float4 v = *(const float4*)&in[id];
        __half2 h0 = __floats2half2_rn(v.x, v.y);
        __half2 h1 = __floats2half2_rn(v.z, v.w);
        uint2 u = {*(uint32_t*)&h0, *(uint32_t*)&h1};
        *(uint2*)&out[id] = u;
    } else {
        for (int i = id; i < n; i++) out[i] = __float2half(in[i]);
    }
}

// ---------------------------------------------------------------------------
// FP16 GEMM: block 128(o) x 128(p) x 64(k), 8 warps 2x4, warp tile 64x32
// (R12 fragment structure). 2-stage cp.async pipeline with k64 tiles:
// half the barrier count, 2x independent work per phase. 70 KB smem -> 2 CTA/SM.
// ---------------------------------------------------------------------------
#define ASTR 72
#define BSTR 136
#define GEMM_A_ELEMS (128 * ASTR)          // 9216 halfs / stage
#define GEMM_B_ELEMS (64 * BSTR)           // 8704 halfs / stage
#define GEMM_SMEM ((2 * (GEMM_A_ELEMS + GEMM_B_ELEMS)) * 2)  // 71680 bytes

template<bool HALF_OUT>
__global__ __launch_bounds__(256, 2) void gemm_f16_kernel(
    const __half* __restrict__ X, const __half* __restrict__ W,
    const float* __restrict__ bias, void* __restrict__ OutV,
    int Kdim, int Odim)
{
    const int p0 = blockIdx.x * 128;
    const int o0 = blockIdx.y * 128;
    const int b  = blockIdx.z;

    const __half* Xb = X + (size_t)b * Kdim * HWPIX;

    extern __shared__ __half gsh[];
    __half* Asb = gsh;
    __half* Bsb = gsh + 2 * GEMM_A_ELEMS;

    const int tid = threadIdx.x;
    const int wid = tid >> 5;
    const int lane = tid & 31;
    const int wm = wid & 1;
    const int wn = wid >> 1;
    const int lr = lane >> 2;
    const int lc = lane & 3;

    float acc[4][4][4];
    #pragma unroll
    for (int i = 0; i < 4; i++)
        #pragma unroll
        for (int j = 0; j < 4; j++)
            #pragma unroll
            for (int r = 0; r < 4; r++) acc[i][j][r] = 0.f;

    const int nkt = Kdim / 64;

    auto stage = [&](int kt, int buf) {
        const int k0 = kt * 64;
        __half* As = Asb + buf * GEMM_A_ELEMS;
        __half* Bs = Bsb + buf * GEMM_B_ELEMS;
        // A: 128 rows x 64 k = 1024 x 16B chunks
        #pragma unroll
        for (int i = 0; i < 4; i++) {
            int id = tid + i * 256;
            int o = id >> 3;
            int c8 = (id & 7) * 8;
            cp16_ca(&As[o * ASTR + c8],
                    &W[(size_t)(o0 + o) * Kdim + k0 + c8], true);
        }
        // B: 64 rows x 128 p = 1024 x 16B chunks
        #pragma unroll
        for (int i = 0; i < 4; i++) {
            int id = tid + i * 256;
            int row = id >> 4;
            int ch = (id & 15) * 8;
            bool ok = (p0 + ch) < HWPIX;
            int col = ok ? (p0 + ch) : (HWPIX - 8);
            cp16_cg(&Bs[row * BSTR + ch],
                    &Xb[(size_t)(k0 + row) * HWPIX + col], ok);
        }
        CP_COMMIT();
    };

    stage(0, 0);
    for (int kt = 0; kt < nkt; kt++) {
        const int buf = kt & 1;
        if (kt + 1 < nkt) {
            stage(kt + 1, buf ^ 1);
            asm volatile("cp.async.wait_group 1;");
        } else {
            asm volatile("cp.async.wait_group 0;");
        }
        __syncthreads();

        __half* As = Asb + buf * GEMM_A_ELEMS;
        __half* Bs = Bsb + buf * GEMM_B_ELEMS;

        #pragma unroll
        for (int kk = 0; kk < 64; kk += 16) {
            uint32_t af[4][4];
            #pragma unroll
            for (int mf = 0; mf < 4; mf++) {
                int row = wm * 64 + mf * 16 + (lane & 15);
                int kof = kk + (lane >> 4) * 8;
                ldsm_x4(af[mf], smem_u32(&As[row * ASTR + kof]));
            }
            uint32_t bf[2][4];
            #pragma unroll
            for (int g = 0; g < 2; g++) {
                int krow = kk + (lane & 15);
                int ncol = wn * 32 + g * 16 + (lane >> 4) * 8;
                ldsm_x4_t(bf[g], smem_u32(&Bs[krow * BSTR + ncol]));
            }
            #pragma unroll
            for (int mf = 0; mf < 4; mf++)
                #pragma unroll
                for (int nf = 0; nf < 4; nf++) {
                    uint32_t bb[2] = {bf[nf >> 1][(nf & 1) * 2],
                                      bf[nf >> 1][(nf & 1) * 2 + 1]};
                    mma_f16(acc[mf][nf], af[mf], bb);
                }
        }
        __syncthreads();
    }

    #pragma unroll
    for (int mf = 0; mf < 4; mf++) {
        int m = o0 + wm * 64 + mf * 16 + lr;
        float bv0 = bias[m];
        float bv1 = bias[m + 8];
        #pragma unroll
        for (int nf = 0; nf < 4; nf++) {
            int n = p0 + wn * 32 + nf * 8 + 2 * lc;
            if (n < HWPIX) {
                if (HALF_OUT) {
                    __half* Ob = (__half*)OutV + (size_t)b * Odim * HWPIX;
                    __half2 r0 = __floats2half2_rn(acc[mf][nf][0] + bv0,
                                                   acc[mf][nf][1] + bv0);
                    __half2 r1 = __floats2half2_rn(acc[mf][nf][2] + bv1,
                                                   acc[mf][nf][3] + bv1);
                    *(__half2*)&Ob[(size_t)m * HWPIX + n] = r0;
                    *(__half2*)&Ob[(size_t)(m + 8) * HWPIX + n] = r1;
                } else {
                    float* Ob = (float*)OutV + (size_t)b * Odim * HWPIX;
                    float2 r0 = {acc[mf][nf][0] + bv0, acc[mf][nf][1] + bv0};
                    float2 r1 = {acc[mf][nf][2] + bv1, acc[mf][nf][3] + bv1};
                    *(float2*)&Ob[(size_t)m * HWPIX + n] = r0;
                    *(float2*)&Ob[(size_t)(m + 8) * HWPIX + n] = r1;
                }
            }
        }
    }
}

// ---------------------------------------------------------------------------
// Depthwise 3x3 (SAME) on half data, 4 px per thread (unchanged)
// ---------------------------------------------------------------------------
__global__ __launch_bounds__(256) void dwconv_kernel(
    const float* __restrict__ wdw, const float* __restrict__ bdw)
{
    int idx = blockIdx.x * blockDim.x + threadIdx.x;
    if (idx >= BATCH * CDIM * HH * (WW / 4)) return;
    int w0 = (idx % (WW / 4)) * 4;
    int h  = (idx / (WW / 4)) % HH;
    int c  = (idx / (WW / 4 * HH)) % CDIM;
    int b  = idx / (WW / 4 * HH * CDIM);

    const __half* v = g_qkvh + ((size_t)b * 3 * CDIM + 2 * CDIM + c) * HWPIX;

    float r[3][6];
    #pragma unroll
    for (int dy = 0; dy < 3; dy++) {
        int hh = h + dy - 1;
        if (hh >= 0 && hh < HH) {
            const __half* row = v + hh * WW;
            __half2 m0 = *(const __half2*)&row[w0];
            __half2 m1 = *(const __half2*)&row[w0 + 2];
            r[dy][0] = (w0 > 0) ? __half2float(row[w0 - 1]) : 0.f;
            r[dy][1] = __half2float(__low2half(m0));
            r[dy][2] = __half2float(__high2half(m0));
            r[dy][3] = __half2float(__low2half(m1));
            r[dy][4] = __half2float(__high2half(m1));
            r[dy][5] = (w0 + 4 < WW) ? __half2float(row[w0 + 4]) : 0.f;
        } else {
            #pragma unroll
            for (int j = 0; j < 6; j++) r[dy][j] = 0.f;
        }
    }

    float wv[3][3];
    #pragma unroll
    for (int dy = 0; dy < 3; dy++)
        #pragma unroll
        for (int dx = 0; dx < 3; dx++)
            wv[dy][dx] = wdw[c * 9 + dy * 3 + dx];

    float bb = bdw[c];
    float o[4];
    #pragma unroll
    for (int j = 0; j < 4; j++) {
        float s = bb + r[1][j + 1];
        #pragma unroll
        for (int dy = 0; dy < 3; dy++)
            #pragma unroll
            for (int dx = 0; dx < 3; dx++)
                s += wv[dy][dx] * r[dy][j + dx];
        o[j] = s;
    }

    __half* out = g_v2h + ((size_t)b * CDIM + c) * HWPIX + h * WW + w0;
    __half2 o0 = __floats2half2_rn(o[0], o[1]);
    __half2 o1 = __floats2half2_rn(o[2], o[3]);
    *(__half2*)&out[0] = o0;
    *(__half2*)&out[2] = o1;
}

// ---------------------------------------------------------------------------
// FP16 stripe attention (exact R12 best-kernel version): lean mainloop,
// ldmatrix K/V frags, f16x2 softmax, ones-row rowsum via PV MMA.
// 13 warps, 16-row q-tiles (2 rounds).
// ---------------------------------------------------------------------------
#define KHS 40
#define VTS 408
#define VROWS_V 40           // 32 data + ones row + 7 zero rows
#define OTS 400
#define QROWS 400            // 392 + 8 pad rows (zeros)
#define ATT_THREADS 416      // 13 warps
#define ATT_Q_OFF 0
#define ATT_K_OFF (QROWS * KHS)
#define ATT_V_OFF (2 * QROWS * KHS)
#define ATT_O_OFF (2 * QROWS * KHS + VROWS_V * VTS)
#define ATT_SMEM ((2 * QROWS * KHS + VROWS_V * VTS + HDIM * OTS) * 2)

__global__ __launch_bounds__(ATT_THREADS, 1) void attn_mma_kernel()
{
    extern __shared__ __half shh[];
    __half* Qsh  = shh + ATT_Q_OFF;   // [400][40]  (token-major, pre-scaled)
    __half* Ksh  = shh + ATT_K_OFF;   // [400][40]
    __half* Vt   = shh + ATT_V_OFF;   // [40][408]  (channel-major + ones row)
    __half* OshT = shh + ATT_O_OFF;   // [32][400]

    const int s = blockIdx.x;
    const int head = blockIdx.y;
    const int b = blockIdx.z;
    const bool wmode = (head >= NHEADS / 2);

    const int tid = threadIdx.x;
    const int wid = tid >> 5;
    const int lane = tid & 31;
    const int lr = lane >> 2;
    const int lc = lane & 3;

    const __half* qbase = g_qkvh + ((size_t)b * 3 * CDIM + head * HDIM) * HWPIX;
    const __half* kbase = g_qkvh + ((size_t)b * 3 * CDIM + CDIM + head * HDIM) * HWPIX;
    const __half* vbase = g_v2h + ((size_t)b * CDIM + head * HDIM) * HWPIX;

    if (!wmode) {
        const int s392 = s * NTOK;
        for (int idx = tid; idx < HDIM * (NTOK / 8); idx += ATT_THREADS) {
            int c = idx / (NTOK / 8);
            int t0 = (idx - c * (NTOK / 8)) * 8;
            size_t g = (size_t)c * HWPIX + s392 + t0;
            uint4 q8 = *(const uint4*)(qbase + g);
            uint4 k8 = *(const uint4*)(kbase + g);
            uint4 v8 = *(const uint4*)(vbase + g);
            const __half* qh = (const __half*)&q8;
            const __half* kh = (const __half*)&k8;
            #pragma unroll
            for (int j = 0; j < 8; j++) {
                Qsh[(t0 + j) * KHS + c] =
                    __float2half(__half2float(qh[j]) * QSCALE);
                Ksh[(t0 + j) * KHS + c] = kh[j];
            }
            *(uint4*)(Vt + c * VTS + t0) = v8;
        }
    } else {
        for (int idx = tid; idx < NTOK * HDIM; idx += ATT_THREADS) {
            int c = idx / NTOK;
            int r = idx - c * NTOK;
            int rq = r / SWID;
            int pix = rq * WW + s * SWID + (r - rq * SWID);
            size_t g = (size_t)c * HWPIX + pix;
            Qsh[r * KHS + c] = __float2half(__half2float(qbase[g]) * QSCALE);
            Ksh[r * KHS + c] = kbase[g];
            Vt[c * VTS + r] = vbase[g];
        }
    }
    // Zero Q pad rows 392..399
    for (int idx = tid; idx < (QROWS - NTOK) * KHS; idx += ATT_THREADS)
        Qsh[NTOK * KHS + idx] = __half(0.f);
    // V rows 32..39: row 32 = ones (rowsum column), rows 33..39 = zero
    for (int idx = tid; idx < (VROWS_V - HDIM) * VTS; idx += ATT_THREADS) {
        int rr = idx / VTS;
        Vt[(HDIM + rr) * VTS + (idx - rr * VTS)] =
            (rr == 0) ? __half(1.f) : __half(0.f);
    }
    __syncthreads();

    for (int mt = wid; mt < 25; mt += 13) {
        int q0 = mt * 16;

        uint32_t aq[2][4];
        #pragma unroll
        for (int kf = 0; kf < 2; kf++)
            ldsm_x4(aq[kf], smem_u32(&Qsh[(q0 + (lane & 15)) * KHS +
                                          kf * 16 + (lane >> 4) * 8]));

        float oacc[5][4];
        #pragma unroll
        for (int i = 0; i < 5; i++)
            #pragma unroll
            for (int j = 0; j < 4; j++) oacc[i][j] = 0.f;

        const int g2 = lane >> 3;       // 0..3
        const int r8 = lane & 7;        // 0..7
        const int l16 = lane & 15;

        for (int kt = 0; kt < 7; kt++) {
            const int t0 = kt * 56;
            uint32_t pA[3][4];
            uint32_t pA8[2];

            // S = Q @ K^T per 8-token n-tile; f16x2 softmax; pack A-frags
            #pragma unroll
            for (int nf = 0; nf < 7; nf++) {
                float sf4[4] = {0.f, 0.f, 0.f, 0.f};
                uint32_t kb[4];
                ldsm_x4(kb, smem_u32(&Ksh[(t0 + nf * 8 + r8) * KHS + g2 * 8]));
                {
                    uint32_t b0[2] = {kb[0], kb[1]};
                    uint32_t b1[2] = {kb[2], kb[3]};
                    mma_f16(sf4, aq[0], b0);
                    mma_f16(sf4, aq[1], b1);
                }
                uint32_t u01, u23;
                asm("cvt.rn.f16x2.f32 %0, %1, %2;"
                    : "=r"(u01) : "f"(sf4[1]), "f"(sf4[0]));
                asm("cvt.rn.f16x2.f32 %0, %1, %2;"
                    : "=r"(u23) : "f"(sf4[3]), "f"(sf4[2]));
                asm("min.f16x2 %0, %0, %1;" : "+r"(u01) : "r"(HCLAMP14));
                asm("min.f16x2 %0, %0, %1;" : "+r"(u23) : "r"(HCLAMP14));
                asm("ex2.approx.f16x2 %0, %0;" : "+r"(u01));
                asm("ex2.approx.f16x2 %0, %0;" : "+r"(u23));
                if (nf == 6) {
                    pA8[0] = u01; pA8[1] = u23;
                } else if ((nf & 1) == 0) {
                    pA[nf >> 1][0] = u01; pA[nf >> 1][1] = u23;
                } else {
                    pA[nf >> 1][2] = u01; pA[nf >> 1][3] = u23;
                }
            }

            // O += P @ V (V b-frags via ldmatrix; vf=4 = rowsum column)
            #pragma unroll
            for (int ch = 0; ch < 3; ch++) {
                const int colb = t0 + ch * 16;
                uint32_t v0[4], v1[4], v2[2];
                ldsm_x4(v0, smem_u32(&Vt[((g2 >> 1) * 8 + r8) * VTS +
                                         colb + (g2 & 1) * 8]));
                ldsm_x4(v1, smem_u32(&Vt[(16 + (g2 >> 1) * 8 + r8) * VTS +
                                         colb + (g2 & 1) * 8]));
                ldsm_x2(v2, smem_u32(&Vt[(HDIM + (l16 & 7)) * VTS +
                                         colb + (l16 >> 3) * 8]));
                {
                    uint32_t b0[2] = {v0[0], v0[1]};
                    uint32_t b1[2] = {v0[2], v0[3]};
                    uint32_t b2[2] = {v1[0], v1[1]};
                    uint32_t b3[2] = {v1[2], v1[3]};
                    uint32_t b4[2] = {v2[0], v2[1]};
                    mma_f16(oacc[0], pA[ch], b0);
                    mma_f16(oacc[1], pA[ch], b1);
                    mma_f16(oacc[2], pA[ch], b2);
                    mma_f16(oacc[3], pA[ch], b3);
                    mma_f16(oacc[4], pA[ch], b4);
                }
            }
            // k8 tail (tokens t0+48..55)
            {
                uint32_t w4[4], w1;
                ldsm_x4(w4, smem_u32(&Vt[(g2 * 8 + r8) * VTS + t0 + 48]));
                ldsm_x1(w1, smem_u32(&Vt[(HDIM + r8) * VTS + t0 + 48]));
                mma_f16_k8(oacc[0], pA8, w4[0]);
                mma_f16_k8(oacc[1], pA8, w4[1]);
                mma_f16_k8(oacc[2], pA8, w4[2]);
                mma_f16_k8(oacc[3], pA8, w4[3]);
                mma_f16_k8(oacc[4], pA8, w1);
            }
        }

        // l lives in output column 32: lanes with lc==0, reg oacc[4][0]/[2]
        float l0 = __shfl_sync(0xffffffffu, oacc[4][0], lane & 28);
        float l1 = __shfl_sync(0xffffffffu, oacc[4][2], lane & 28);
        float inv0 = 1.f / l0, inv1 = 1.f / l1;

        int r0 = q0 + lr, r1 = q0 + lr + 8;
        #pragma unroll
        for (int nf = 0; nf < 4; nf++) {
            int c = nf * 8 + 2 * lc;
            OshT[c * OTS + r0]       = __float2half(oacc[nf][0] * inv0);
            OshT[(c + 1) * OTS + r0] = __float2half(oacc[nf][1] * inv0);
            OshT[c * OTS + r1]       = __float2half(oacc[nf][2] * inv1);
            OshT[(c + 1) * OTS + r1] = __float2half(oacc[nf][3] * inv1);
        }
    }
    __syncthreads();

    // Writeback
    __half* obase = g_atth + ((size_t)b * CDIM + head * HDIM) * HWPIX;
    if (!wmode) {
        const int s392 = s * NTOK;
        for (int idx = tid; idx < HDIM * (NTOK / 8); idx += ATT_THREADS) {
            int c = idx / (NTOK / 8);
            int t0 = (idx - c * (NTOK / 8)) * 8;
            uint4 o8 = *(const uint4*)(OshT + c * OTS + t0);
            *(uint4*)(obase + (size_t)c * HWPIX + s392 + t0) = o8;
        }
    } else {
        for (int idx = tid; idx < NTOK * HDIM; idx += ATT_THREADS) {
            int c = idx / NTOK;
            int r = idx - c * NTOK;
            int rq = r / SWID;
            int pix = rq * WW + s * SWID + (r - rq * SWID);
            obase[(size_t)c * HWPIX + pix] = OshT[c * OTS + r];
        }
    }
}

// ---------------------------------------------------------------------------
extern "C" void kernel_launch(void* const* d_in, const int* in_sizes, int n_in,
                              void* d_out, int out_size)
{
    const float* x      = (const float*)d_in[0];
    const float* w_qkv  = (const float*)d_in[1];
    const float* b_qkv  = (const float*)d_in[2];
    const float* w_dw   = (const float*)d_in[3];
    const float* b_dw   = (const float*)d_in[4];
    const float* w_proj = (const float*)d_in[5];
    const float* b_proj = (const float*)d_in[6];
    float* out = (float*)d_out;

    __half* xh;   cudaGetSymbolAddress((void**)&xh, g_xh);
    __half* wqh;  cudaGetSymbolAddress((void**)&wqh, g_wqh);
    __half* wph;  cudaGetSymbolAddress((void**)&wph, g_wph);
    __half* qkvh; cudaGetSymbolAddress((void**)&qkvh, g_qkvh);
    __half* atth; cudaGetSymbolAddress((void**)&atth, g_atth);

    cudaFuncSetAttribute(gemm_f16_kernel<true>,
                         cudaFuncAttributeMaxDynamicSharedMemorySize, GEMM_SMEM);
    cudaFuncSetAttribute(gemm_f16_kernel<false>,
                         cudaFuncAttributeMaxDynamicSharedMemorySize, GEMM_SMEM);
    cudaFuncSetAttribute(attn_mma_kernel,
                         cudaFuncAttributeMaxDynamicSharedMemorySize, ATT_SMEM);

    // 0. convert inputs to half
    {
        int n = BATCH * CDIM * HWPIX;
        f2h_kernel<<<(n / 4 + 255) / 256, 256>>>(x, xh, n);
        n = 3 * CDIM * CDIM;
        f2h_kernel<<<(n / 4 + 255) / 256, 256>>>(w_qkv, wqh, n);
        n = CDIM * CDIM;
        f2h_kernel<<<(n / 4 + 255) / 256, 256>>>(w_proj, wph, n);
    }
    // 1. qkv = conv1x1(x) -> half
    {
        dim3 grid((HWPIX + 127) / 128, (3 * CDIM) / 128, BATCH);
        gemm_f16_kernel<true><<<grid, 256, GEMM_SMEM>>>(xh, wqh, b_qkv, qkvh,
                                                        CDIM, 3 * CDIM);
    }
    // 2. v2 = v + dwconv(v)
    {
        int n = BATCH * CDIM * HH * (WW / 4);
        dwconv_kernel<<<(n + 255) / 256, 256>>>(w_dw, b_dw);
    }
    // 3. fp16 stripe attention -> half
    {
        dim3 grid(NSTRIPE, NHEADS, BATCH);
        attn_mma_kernel<<<grid, ATT_THREADS, ATT_SMEM>>>();
    }
    // 4. out = conv1x1(att) -> fp32
    {
        dim3 grid((HWPIX + 127) / 128, CDIM / 128, BATCH);
        gemm_f16_kernel<false><<<grid, 256, GEMM_SMEM>>>(atth, wph, b_proj, out,
                                                         CDIM, CDIM);
    }
}